// round 2
// baseline (speedup 1.0000x reference)
#include <cuda_runtime.h>
#include <math_constants.h>

#define N_ITERS 3
#define EPS_F 1e-4f

// Scratch for u[i][t][b][d] : 64*320*8*64 floats = 41.9 MB.
// __device__ global is the sanctioned no-alloc workaround.
__device__ float g_u[64 * 320 * 8 * 64];

// Packed fp32x2 FMA (Blackwell): acc.lo += a.lo*b.lo; acc.hi += a.hi*b.hi
__device__ __forceinline__ void ffma2(unsigned long long &acc,
                                      unsigned long long a,
                                      unsigned long long b) {
    asm("fma.rn.f32x2 %0, %1, %2, %0;" : "+l"(acc) : "l"(a), "l"(b));
}

// ---------------------------------------------------------------------------
// Phase 1: u[b,i,t,d] = sum_k W[i,t,d,k] * cat_emb[b,t,k]
// One warp per (i,t) tile. Each lane owns d = {lane, lane+32}, all 8 b.
// W rows streamed straight from global (16B vectors); c staged in smem [b][k]
// and read as broadcast LDS.128. FMAs packed along k via fma.rn.f32x2.
// ---------------------------------------------------------------------------
__global__ __launch_bounds__(256) void compute_u_kernel(
    const float* __restrict__ M_emb,   // [8,64,64]
    const float* __restrict__ Ht,      // [8,256,64]
    const float* __restrict__ W)       // [64,320,64,64]
{
    __shared__ __align__(16) float cs[8][512];   // [warp][b*64+k]
    const int warp = threadIdx.x >> 5;
    const int lane = threadIdx.x & 31;
    const int tile = blockIdx.x * 8 + warp;      // tile = i*320 + t, 0..20479
    const int t    = tile % 320;

    // Stage c[b][k] for this tile's t (coalesced float2 loads, conflict-free stores)
    const float* src;
    int bstride;
    if (t < 64) { src = M_emb + t * 64;        bstride = 64 * 64;  }
    else        { src = Ht + (t - 64) * 64;    bstride = 256 * 64; }
#pragma unroll
    for (int b = 0; b < 8; ++b) {
        float2 v = *(const float2*)(src + b * bstride + 2 * lane);
        *(float2*)&cs[warp][b * 64 + 2 * lane] = v;
    }
    __syncwarp();

    // W row pointers for d = lane and d = lane+32 (16B = 4 floats per ulonglong2)
    const ulonglong2* W0 =
        (const ulonglong2*)(W + ((size_t)tile * 64 + lane) * 64);
    const ulonglong2* W1 = W0 + 512;   // +32 rows * 64 floats / 4

    unsigned long long acc[2][8];
#pragma unroll
    for (int h = 0; h < 2; ++h)
#pragma unroll
        for (int b = 0; b < 8; ++b) acc[h][b] = 0ull;

#pragma unroll
    for (int c = 0; c < 16; ++c) {        // k chunk of 4
        ulonglong2 w0 = W0[c];
        ulonglong2 w1 = W1[c];
#pragma unroll
        for (int b = 0; b < 8; ++b) {
            ulonglong2 cv = *(const ulonglong2*)&cs[warp][b * 64 + c * 4];
            ffma2(acc[0][b], w0.x, cv.x);
            ffma2(acc[0][b], w0.y, cv.y);
            ffma2(acc[1][b], w1.x, cv.x);
            ffma2(acc[1][b], w1.y, cv.y);
        }
    }

    // Epilogue: u[tile][b][d] = lo+hi of packed accumulator
    float* up = g_u + (size_t)tile * 512;
#pragma unroll
    for (int b = 0; b < 8; ++b) {
        unsigned long long a0 = acc[0][b];
        unsigned long long a1 = acc[1][b];
        float l0 = __uint_as_float((unsigned)a0);
        float h0 = __uint_as_float((unsigned)(a0 >> 32));
        float l1 = __uint_as_float((unsigned)a1);
        float h1 = __uint_as_float((unsigned)(a1 >> 32));
        up[b * 64 + lane]      = l0 + h0;
        up[b * 64 + lane + 32] = l1 + h1;
    }
}

// ---------------------------------------------------------------------------
// Phase 2: 3 routing iterations, one CTA per (b,i).
// u slice (320x64) lives in shared memory (padded to 65 -> conflict-free both
// for t-parallel logit dots and d-parallel weighted sums).
// ---------------------------------------------------------------------------
__global__ __launch_bounds__(256) void iterate_kernel(
    const float* __restrict__ m_init,  // [8,64,64]
    float* __restrict__ out)           // [8,64,64]
{
    extern __shared__ float sm[];
    float* us    = sm;               // 320*65
    float* sb    = us + 320 * 65;    // 320 (logits -> exp weights)
    float* smm   = sb + 320;         // 64  (current m)
    float* red   = smm + 64;         // 16  (reduction scratch)
    float* spart = red + 16;         // 256 (s partials / s values)

    const int tid  = threadIdx.x;
    const int lane = tid & 31;
    const int wrp  = tid >> 5;
    const int b    = blockIdx.x >> 6;
    const int i    = blockIdx.x & 63;

    // Load u slice: g_u[(i*320+t)*512 + b*64 + d]
    const float* uslice = g_u + (size_t)i * 320 * 512 + b * 64;
    for (int idx = tid; idx < 320 * 64; idx += 256) {
        int t = idx >> 6, d = idx & 63;
        us[t * 65 + d] = uslice[(size_t)t * 512 + d];
    }
    if (tid < 64) smm[tid] = m_init[((size_t)b * 64 + i) * 64 + tid];
    __syncthreads();

    for (int it = 0; it < N_ITERS; ++it) {
        // logits: b_t = sum_d m[d] * u[t][d]
        for (int t = tid; t < 320; t += 256) {
            float a = 0.f;
            const float* ur = us + t * 65;
#pragma unroll 8
            for (int d = 0; d < 64; ++d) a += smm[d] * ur[d];
            sb[t] = a;
        }
        __syncthreads();

        // softmax max
        float lm = -CUDART_INF_F;
        for (int t = tid; t < 320; t += 256) lm = fmaxf(lm, sb[t]);
#pragma unroll
        for (int o = 16; o; o >>= 1)
            lm = fmaxf(lm, __shfl_xor_sync(0xffffffffu, lm, o));
        if (lane == 0) red[wrp] = lm;
        __syncthreads();
        if (tid == 0) {
            float mx = red[0];
            for (int w = 1; w < 8; ++w) mx = fmaxf(mx, red[w]);
            red[8] = mx;
        }
        __syncthreads();
        float mx = red[8];

        // exp + sum
        float ls = 0.f;
        for (int t = tid; t < 320; t += 256) {
            float e = expf(sb[t] - mx);
            sb[t] = e;
            ls += e;
        }
#pragma unroll
        for (int o = 16; o; o >>= 1) ls += __shfl_xor_sync(0xffffffffu, ls, o);
        if (lane == 0) red[wrp] = ls;
        __syncthreads();
        if (tid == 0) {
            float s = 0.f;
            for (int w = 0; w < 8; ++w) s += red[w];
            red[8] = 1.f / s;
        }
        __syncthreads();
        float inv = red[8];

        // s_d = sum_t alph_t * u[t][d], split t into 4 chunks of 80
        {
            int d = tid & 63, q = tid >> 6;
            float p = 0.f;
            int t0 = q * 80;
            for (int t = t0; t < t0 + 80; ++t) p += sb[t] * us[t * 65 + d];
            spart[tid] = p;
        }
        __syncthreads();
        if (tid < 64) {
            float sr = (spart[tid] + spart[tid + 64] +
                        spart[tid + 128] + spart[tid + 192]) * inv;
            spart[tid] = tanhf(sr);
        }
        __syncthreads();
        // ||s||^2
        if (tid < 32) {
            float v = spart[tid] * spart[tid] +
                      spart[tid + 32] * spart[tid + 32];
#pragma unroll
            for (int o = 16; o; o >>= 1) v += __shfl_xor_sync(0xffffffffu, v, o);
            if (tid == 0) red[8] = v;
        }
        __syncthreads();
        if (tid < 64) {
            float n = sqrtf(red[8]) + EPS_F;
            smm[tid] = (n * n) / (1.f + n * n) * (spart[tid] / n);
        }
        __syncthreads();
    }

    if (tid < 64) out[((size_t)b * 64 + i) * 64 + tid] = smm[tid];
}

// ---------------------------------------------------------------------------
extern "C" void kernel_launch(void* const* d_in, const int* in_sizes, int n_in,
                              void* d_out, int out_size) {
    const float* M_emb  = (const float*)d_in[0];  // [8,64,64]
    const float* Ht     = (const float*)d_in[1];  // [8,256,64]
    const float* m_init = (const float*)d_in[2];  // [8,64,64]
    const float* W      = (const float*)d_in[3];  // [64,320,64,64]
    float* out = (float*)d_out;

    // Phase 1: 20480 tiles, 8 warps (tiles) per CTA
    compute_u_kernel<<<2560, 256>>>(M_emb, Ht, W);

    // Phase 2: one CTA per (b,i)
    const int smem_bytes = (320 * 65 + 320 + 64 + 16 + 256) * 4;  // 85824
    cudaFuncSetAttribute(iterate_kernel,
                         cudaFuncAttributeMaxDynamicSharedMemorySize,
                         smem_bytes);
    iterate_kernel<<<512, 256, smem_bytes>>>(m_init, out);
}

// round 5
// speedup vs baseline: 1.0854x; 1.0854x over previous
#include <cuda_runtime.h>
#include <math_constants.h>

#define N_ITERS 3
#define EPS_F 1e-4f

// Scratch u in [b][i][t][d] layout: 8*64*320*64 floats = 41.9 MB.
__device__ float g_u[8 * 64 * 320 * 64];

// Packed fp32x2 FMA (Blackwell): acc.lo += a.lo*b.lo; acc.hi += a.hi*b.hi
__device__ __forceinline__ void ffma2(unsigned long long &acc,
                                      unsigned long long a,
                                      unsigned long long b) {
    asm("fma.rn.f32x2 %0, %1, %2, %0;" : "+l"(acc) : "l"(a), "l"(b));
}

// Streaming (evict-first) 16B load of a packed f32x2 pair vector.
__device__ __forceinline__ void ldcs_v2u64(const void* p,
                                           unsigned long long &x,
                                           unsigned long long &y) {
    asm("ld.global.cs.v2.u64 {%0,%1}, [%2];" : "=l"(x), "=l"(y) : "l"(p));
}

// ---------------------------------------------------------------------------
// Phase 1: u[b,i,t,d] = sum_k W[i,t,d,k] * cat_emb[b,t,k]
// One warp per (i-PAIR, t): computes tiles (p,t) and (p+32,t) so the staged
// cat_emb smem (and its LDS broadcasts) is amortized over 2x the W stream.
// Lane owns d = {lane, lane+32}; 4 independent W load streams per warp.
// W streamed with .cs (read-once) so g_u stays resident in L2 for phase 2.
// ---------------------------------------------------------------------------
__global__ __launch_bounds__(256, 2) void compute_u_kernel(
    const float* __restrict__ M_emb,   // [8,64,64]
    const float* __restrict__ Ht,      // [8,256,64]
    const float* __restrict__ W)       // [64,320,64,64]
{
    __shared__ __align__(16) float cs[8][512];   // [warp][b*64+k]
    const int warp = threadIdx.x >> 5;
    const int lane = threadIdx.x & 31;
    const int job  = blockIdx.x * 8 + warp;      // 0..10239
    const int p    = job / 320;                  // i-pair id: i = p, p+32
    const int t    = job % 320;

    // Stage c[b][k] for this t (coalesced float2 loads, conflict-free stores)
    const float* src;
    int bstride;
    if (t < 64) { src = M_emb + t * 64;        bstride = 64 * 64;  }
    else        { src = Ht + (t - 64) * 64;    bstride = 256 * 64; }
#pragma unroll
    for (int b = 0; b < 8; ++b) {
        float2 v = *(const float2*)(src + b * bstride + 2 * lane);
        *(float2*)&cs[warp][b * 64 + 2 * lane] = v;
    }
    __syncwarp();

    const int tileA = p * 320 + t;
    const int tileB = (p + 32) * 320 + t;
    const ulonglong2* WA0 =
        (const ulonglong2*)(W + ((size_t)tileA * 64 + lane) * 64);
    const ulonglong2* WA1 = WA0 + 512;           // +32 d-rows
    const ulonglong2* WB0 =
        (const ulonglong2*)(W + ((size_t)tileB * 64 + lane) * 64);
    const ulonglong2* WB1 = WB0 + 512;

    // acc[i2][h][b] : i2 = which i of the pair, h = d-half
    unsigned long long acc[2][2][8];
#pragma unroll
    for (int i2 = 0; i2 < 2; ++i2)
#pragma unroll
        for (int h = 0; h < 2; ++h)
#pragma unroll
            for (int b = 0; b < 8; ++b) acc[i2][h][b] = 0ull;

#pragma unroll
    for (int c = 0; c < 16; ++c) {        // k chunk of 4
        unsigned long long a0x, a0y, a1x, a1y, b0x, b0y, b1x, b1y;
        ldcs_v2u64(WA0 + c, a0x, a0y);
        ldcs_v2u64(WA1 + c, a1x, a1y);
        ldcs_v2u64(WB0 + c, b0x, b0y);
        ldcs_v2u64(WB1 + c, b1x, b1y);
#pragma unroll
        for (int b = 0; b < 8; ++b) {
            ulonglong2 cv = *(const ulonglong2*)&cs[warp][b * 64 + c * 4];
            ffma2(acc[0][0][b], a0x, cv.x);
            ffma2(acc[0][0][b], a0y, cv.y);
            ffma2(acc[0][1][b], a1x, cv.x);
            ffma2(acc[0][1][b], a1y, cv.y);
            ffma2(acc[1][0][b], b0x, cv.x);
            ffma2(acc[1][0][b], b0y, cv.y);
            ffma2(acc[1][1][b], b1x, cv.x);
            ffma2(acc[1][1][b], b1y, cv.y);
        }
    }

    // u[b][tile][d]  (g_u index = (b*20480 + tile)*64 + d)
#pragma unroll
    for (int i2 = 0; i2 < 2; ++i2) {
        const int tile = i2 ? tileB : tileA;
#pragma unroll
        for (int b = 0; b < 8; ++b) {
            float* up = g_u + ((size_t)b * 20480 + tile) * 64;
            unsigned long long v0 = acc[i2][0][b];
            unsigned long long v1 = acc[i2][1][b];
            up[lane]      = __uint_as_float((unsigned)v0) +
                            __uint_as_float((unsigned)(v0 >> 32));
            up[lane + 32] = __uint_as_float((unsigned)v1) +
                            __uint_as_float((unsigned)(v1 >> 32));
        }
    }
}

// ---------------------------------------------------------------------------
// Phase 2: 3 routing iterations, one CTA of 512 threads per (b,i).
// u slice (320x64) register-resident: warp w owns t in [w*20, w*20+20),
// lane owns d = {2*lane, 2*lane+1}. Logits via warp shuffles; weighted sums
// as register FMAs. smem ~6 KB -> no occupancy cap.
// ---------------------------------------------------------------------------
__global__ __launch_bounds__(512) void iterate_kernel(
    const float* __restrict__ m_init,  // [8,64,64]
    float* __restrict__ out)           // [8,64,64]
{
    __shared__ float sb[320];          // logits -> exp weights
    __shared__ float smm[64];          // current m
    __shared__ float part[16][64];     // per-warp s partials
    __shared__ float red[16];          // per-warp reduction scratch
    __shared__ float sval[64];         // tanh(s)
    __shared__ float bc[2];            // broadcast scalars

    const int tid  = threadIdx.x;
    const int lane = tid & 31;
    const int w    = tid >> 5;         // 0..15

    // Register-resident u slice
    const float* uslice = g_u + (size_t)blockIdx.x * 320 * 64;
    float2 ur[20];
#pragma unroll
    for (int j = 0; j < 20; ++j)
        ur[j] = *(const float2*)(uslice + (w * 20 + j) * 64 + 2 * lane);

    if (tid < 64) smm[tid] = m_init[(size_t)blockIdx.x * 64 + tid];
    __syncthreads();

    for (int it = 0; it < N_ITERS; ++it) {
        // ---- logits: b_t = sum_d m[d]*u[t][d] (warp butterfly per t) ----
        float2 m2 = *(const float2*)&smm[2 * lane];
#pragma unroll
        for (int j = 0; j < 20; ++j) {
            float v = fmaf(m2.x, ur[j].x, m2.y * ur[j].y);
#pragma unroll
            for (int o = 16; o; o >>= 1)
                v += __shfl_xor_sync(0xffffffffu, v, o);
            if (lane == j) sb[w * 20 + j] = v;
        }
        __syncthreads();

        // ---- softmax max ----
        float lv = (tid < 320) ? sb[tid] : -CUDART_INF_F;
        {
            float x = lv;
#pragma unroll
            for (int o = 16; o; o >>= 1)
                x = fmaxf(x, __shfl_xor_sync(0xffffffffu, x, o));
            if (lane == 0) red[w] = x;
        }
        __syncthreads();
        if (w == 0) {
            float x = (lane < 16) ? red[lane] : -CUDART_INF_F;
#pragma unroll
            for (int o = 8; o; o >>= 1)
                x = fmaxf(x, __shfl_xor_sync(0xffffffffu, x, o));
            if (lane == 0) bc[0] = x;
        }
        __syncthreads();
        const float mx = bc[0];

        // ---- exp + sum ----
        float e = 0.f;
        if (tid < 320) { e = __expf(lv - mx); sb[tid] = e; }
        {
            float x = e;
#pragma unroll
            for (int o = 16; o; o >>= 1)
                x += __shfl_xor_sync(0xffffffffu, x, o);
            if (lane == 0) red[w] = x;
        }
        __syncthreads();
        if (w == 0) {
            float x = (lane < 16) ? red[lane] : 0.f;
#pragma unroll
            for (int o = 8; o; o >>= 1)
                x += __shfl_xor_sync(0xffffffffu, x, o);
            if (lane == 0) bc[1] = 1.f / x;
        }
        __syncthreads();
        const float inv = bc[1];

        // ---- weighted sum partials: part[w][d] = sum_{t in warp} e_t*u[t][d]
        {
            float a0 = 0.f, a1 = 0.f, b0 = 0.f, b1 = 0.f;
#pragma unroll
            for (int j = 0; j < 20; j += 2) {
                float e0 = sb[w * 20 + j];
                float e1 = sb[w * 20 + j + 1];
                a0 = fmaf(e0, ur[j].x, a0);
                a1 = fmaf(e0, ur[j].y, a1);
                b0 = fmaf(e1, ur[j + 1].x, b0);
                b1 = fmaf(e1, ur[j + 1].y, b1);
            }
            float2 pr = make_float2(a0 + b0, a1 + b1);
            *(float2*)&part[w][2 * lane] = pr;
        }
        __syncthreads();

        // ---- s_d = tanh(inv * sum_w part[w][d]) ----
        if (tid < 64) {
            float s = 0.f;
#pragma unroll
            for (int ww = 0; ww < 16; ++ww) s += part[ww][tid];
            sval[tid] = tanhf(s * inv);
        }
        __syncthreads();

        // ---- ||s||^2 ----
        if (w == 0) {
            float v = sval[lane] * sval[lane] +
                      sval[lane + 32] * sval[lane + 32];
#pragma unroll
            for (int o = 16; o; o >>= 1)
                v += __shfl_xor_sync(0xffffffffu, v, o);
            if (lane == 0) bc[0] = v;
        }
        __syncthreads();

        // ---- squash ----
        if (tid < 64) {
            float n = sqrtf(bc[0]) + EPS_F;
            smm[tid] = (n * n) / (1.f + n * n) * (sval[tid] / n);
        }
        __syncthreads();
    }

    if (tid < 64) out[(size_t)blockIdx.x * 64 + tid] = smm[tid];
}

// ---------------------------------------------------------------------------
extern "C" void kernel_launch(void* const* d_in, const int* in_sizes, int n_in,
                              void* d_out, int out_size) {
    const float* M_emb  = (const float*)d_in[0];  // [8,64,64]
    const float* Ht     = (const float*)d_in[1];  // [8,256,64]
    const float* m_init = (const float*)d_in[2];  // [8,64,64]
    const float* W      = (const float*)d_in[3];  // [64,320,64,64]
    float* out = (float*)d_out;

    // Phase 1: 10240 warp-jobs (i-pair, t), 8 warps per CTA
    compute_u_kernel<<<1280, 256>>>(M_emb, Ht, W);

    // Phase 2: one CTA per (b,i)
    iterate_kernel<<<512, 512>>>(m_init, out);
}

// round 10
// speedup vs baseline: 1.3917x; 1.2823x over previous
#include <cuda_runtime.h>
#include <math_constants.h>

#define N_ITERS 3
#define EPS_F 1e-4f

#define NT     4      // tiles (t values) per CTA in phase 1
#define PITCH  68     // padded floats per W d-row in smem (bank-conflict-free)

// Scratch u in [b][i][t][d] layout: 8*64*320*64 floats = 41.9 MB.
__device__ float g_u[8 * 64 * 320 * 64];

// Packed fp32x2 FMA (Blackwell): acc.lo += a.lo*b.lo; acc.hi += a.hi*b.hi
__device__ __forceinline__ void ffma2(unsigned long long &acc,
                                      unsigned long long a,
                                      unsigned long long b) {
    asm("fma.rn.f32x2 %0, %1, %2, %0;" : "+l"(acc) : "l"(a), "l"(b));
}

__device__ __forceinline__ void cp_async16(void* smem_dst, const void* gsrc) {
    unsigned s = (unsigned)__cvta_generic_to_shared(smem_dst);
    asm volatile("cp.async.cg.shared.global [%0], [%1], 16;"
                 :: "r"(s), "l"(gsrc) : "memory");
}
__device__ __forceinline__ void cp_async_commit() {
    asm volatile("cp.async.commit_group;" ::: "memory");
}
template <int N>
__device__ __forceinline__ void cp_async_wait() {
    asm volatile("cp.async.wait_group %0;" :: "n"(N) : "memory");
}

// ---------------------------------------------------------------------------
// Phase 1: u[b,i,t,d] = sum_k W[i,t,d,k] * cat_emb[b,t,k]
// CTA (128 thr) = (i, 4 consecutive t) -> 64 KB contiguous W, staged through
// smem with COALESCED cp.async (fixes nL=32 L1tex wavefront saturation of the
// direct strided LDG version). Two 32-d-row stages, double-buffered.
// Warp w computes tile w: lane owns one d-row (PITCH-padded -> 4-phase LDS),
// c broadcast from smem (warp-uniform address, N=1), packed f32x2 FMA,
// coalesced stores.
// ---------------------------------------------------------------------------
__global__ __launch_bounds__(128) void compute_u_kernel(
    const float* __restrict__ M_emb,   // [8,64,64]
    const float* __restrict__ Ht,      // [8,256,64]
    const float* __restrict__ W)       // [64,320,64,64]
{
    extern __shared__ __align__(16) float sm[];
    float* wb[2] = { sm, sm + NT * 32 * PITCH };     // 2 x 8704 floats
    float* csm   = sm + 2 * NT * 32 * PITCH;         // NT*512 floats

    const int tid  = threadIdx.x;
    const int lane = tid & 31;
    const int w    = tid >> 5;                       // warp = local tile
    const int i    = blockIdx.x / 80;
    const int t0   = (blockIdx.x % 80) * NT;
    const float* Wbase = W + ((size_t)i * 320 + t0) * 4096;

    // Issue cp.async for both stages (s: d-rows [32s, 32s+32) of each tile).
    // Granule G (0..2047 per stage): row = G>>4 (tile*32 + r), col = G&15.
    // Consecutive threads -> consecutive 16B in global (coalesced, nL=4).
#pragma unroll
    for (int s = 0; s < 2; ++s) {
#pragma unroll
        for (int g = 0; g < 16; ++g) {
            int G    = g * 128 + tid;
            int row  = G >> 4;                       // 0..127
            int col  = G & 15;
            int tile = row >> 5, r = row & 31;
            const float* src = Wbase + (size_t)tile * 4096 +
                               (s * 32 + r) * 64 + col * 4;
            cp_async16(wb[s] + row * PITCH + col * 4, src);
        }
        cp_async_commit();
    }

    // Stage c[t][b][k] with regular coalesced float4 loads (512 granules).
#pragma unroll
    for (int g = 0; g < 4; ++g) {
        int G = g * 128 + tid;
        int j = G >> 7, b = (G >> 4) & 7, col = G & 15;
        int t = t0 + j;
        const float* src = (t < 64)
            ? M_emb + (size_t)b * 4096  + t * 64        + col * 4
            : Ht    + (size_t)b * 16384 + (t - 64) * 64 + col * 4;
        *(float4*)&csm[j * 512 + b * 64 + col * 4] = *(const float4*)src;
    }

    const int tile_g = i * 320 + t0 + w;             // global tile id
    const float* crow = csm + w * 512;

#pragma unroll
    for (int s = 0; s < 2; ++s) {
        if (s == 0) cp_async_wait<1>(); else cp_async_wait<0>();
        __syncthreads();

        const float* wrow = wb[s] + (w * 32 + lane) * PITCH;
        unsigned long long acc[8];
#pragma unroll
        for (int b = 0; b < 8; ++b) acc[b] = 0ull;

#pragma unroll
        for (int kc = 0; kc < 16; ++kc) {
            ulonglong2 wv = *(const ulonglong2*)(wrow + kc * 4);
#pragma unroll
            for (int b = 0; b < 8; ++b) {
                ulonglong2 cv = *(const ulonglong2*)(crow + b * 64 + kc * 4);
                ffma2(acc[b], wv.x, cv.x);
                ffma2(acc[b], wv.y, cv.y);
            }
        }

        const int d = s * 32 + lane;
#pragma unroll
        for (int b = 0; b < 8; ++b) {
            unsigned long long a = acc[b];
            g_u[((size_t)b * 20480 + tile_g) * 64 + d] =
                __uint_as_float((unsigned)a) +
                __uint_as_float((unsigned)(a >> 32));
        }
    }
}

// ---------------------------------------------------------------------------
// Phase 2: 3 routing iterations, one CTA of 512 threads per (b,i).
// COALESCED u residency: warp w owns t in [20w, 20w+20); per load j the warp
// reads two full contiguous u-rows (512B, nL=4): lane = (half = t-of-pair,
// q = d-quad). Logits: 4-shfl reduction within 16-lane halves. Weighted sums:
// float4 register FMAs + one xor-16 merge.
// ---------------------------------------------------------------------------
__global__ __launch_bounds__(512) void iterate_kernel(
    const float* __restrict__ m_init,  // [8,64,64]
    float* __restrict__ out)           // [8,64,64]
{
    __shared__ float sb[320];          // logits -> exp weights
    __shared__ float smm[64];          // current m
    __shared__ float part[16][64];     // per-warp s partials
    __shared__ float red[16];
    __shared__ float sval[64];
    __shared__ float bc[2];

    const int tid  = threadIdx.x;
    const int lane = tid & 31;
    const int w    = tid >> 5;         // 0..15
    const int half = lane >> 4;        // which t of the row pair
    const int q    = lane & 15;        // d-quad index

    const float* uslice = g_u + (size_t)blockIdx.x * 320 * 64;
    float4 ur[10];
#pragma unroll
    for (int j = 0; j < 10; ++j)
        ur[j] = *(const float4*)(uslice + (w * 20 + j * 2 + half) * 64 + q * 4);

    if (tid < 64) smm[tid] = m_init[(size_t)blockIdx.x * 64 + tid];
    __syncthreads();

    for (int it = 0; it < N_ITERS; ++it) {
        // ---- logits: b_t = sum_d m[d]*u[t][d] ----
        float4 m4 = *(const float4*)&smm[q * 4];
#pragma unroll
        for (int j = 0; j < 10; ++j) {
            float v = fmaf(ur[j].x, m4.x,
                      fmaf(ur[j].y, m4.y,
                      fmaf(ur[j].z, m4.z, ur[j].w * m4.w)));
#pragma unroll
            for (int o = 8; o; o >>= 1)
                v += __shfl_xor_sync(0xffffffffu, v, o);
            if (q == 0) sb[w * 20 + j * 2 + half] = v;
        }
        __syncthreads();

        // ---- softmax max ----
        float lv = (tid < 320) ? sb[tid] : -CUDART_INF_F;
        {
            float x = lv;
#pragma unroll
            for (int o = 16; o; o >>= 1)
                x = fmaxf(x, __shfl_xor_sync(0xffffffffu, x, o));
            if (lane == 0) red[w] = x;
        }
        __syncthreads();
        if (w == 0) {
            float x = (lane < 16) ? red[lane] : -CUDART_INF_F;
#pragma unroll
            for (int o = 8; o; o >>= 1)
                x = fmaxf(x, __shfl_xor_sync(0xffffffffu, x, o));
            if (lane == 0) bc[0] = x;
        }
        __syncthreads();
        const float mx = bc[0];

        // ---- exp + sum ----
        float e = 0.f;
        if (tid < 320) { e = __expf(lv - mx); sb[tid] = e; }
        {
            float x = e;
#pragma unroll
            for (int o = 16; o; o >>= 1)
                x += __shfl_xor_sync(0xffffffffu, x, o);
            if (lane == 0) red[w] = x;
        }
        __syncthreads();
        if (w == 0) {
            float x = (lane < 16) ? red[lane] : 0.f;
#pragma unroll
            for (int o = 8; o; o >>= 1)
                x += __shfl_xor_sync(0xffffffffu, x, o);
            if (lane == 0) bc[1] = 1.f / x;
        }
        __syncthreads();
        const float inv = bc[1];

        // ---- weighted sum: part[w][d] = sum_{t in warp} e_t * u[t][d] ----
        {
            float4 a = make_float4(0.f, 0.f, 0.f, 0.f);
#pragma unroll
            for (int j = 0; j < 10; ++j) {
                float ew = sb[w * 20 + j * 2 + half];
                a.x = fmaf(ew, ur[j].x, a.x);
                a.y = fmaf(ew, ur[j].y, a.y);
                a.z = fmaf(ew, ur[j].z, a.z);
                a.w = fmaf(ew, ur[j].w, a.w);
            }
            a.x += __shfl_xor_sync(0xffffffffu, a.x, 16);
            a.y += __shfl_xor_sync(0xffffffffu, a.y, 16);
            a.z += __shfl_xor_sync(0xffffffffu, a.z, 16);
            a.w += __shfl_xor_sync(0xffffffffu, a.w, 16);
            if (half == 0) *(float4*)&part[w][q * 4] = a;
        }
        __syncthreads();

        // ---- s_d = tanh(inv * sum_w part[w][d]) ----
        if (tid < 64) {
            float s = 0.f;
#pragma unroll
            for (int ww = 0; ww < 16; ++ww) s += part[ww][tid];
            sval[tid] = tanhf(s * inv);
        }
        __syncthreads();

        // ---- ||s||^2 ----
        if (w == 0) {
            float v = sval[lane] * sval[lane] +
                      sval[lane + 32] * sval[lane + 32];
#pragma unroll
            for (int o = 16; o; o >>= 1)
                v += __shfl_xor_sync(0xffffffffu, v, o);
            if (lane == 0) bc[0] = v;
        }
        __syncthreads();

        // ---- squash ----
        if (tid < 64) {
            float n = sqrtf(bc[0]) + EPS_F;
            smm[tid] = (n * n) / (1.f + n * n) * (sval[tid] / n);
        }
        __syncthreads();
    }

    if (tid < 64) out[(size_t)blockIdx.x * 64 + tid] = smm[tid];
}

// ---------------------------------------------------------------------------
extern "C" void kernel_launch(void* const* d_in, const int* in_sizes, int n_in,
                              void* d_out, int out_size) {
    const float* M_emb  = (const float*)d_in[0];  // [8,64,64]
    const float* Ht     = (const float*)d_in[1];  // [8,256,64]
    const float* m_init = (const float*)d_in[2];  // [8,64,64]
    const float* W      = (const float*)d_in[3];  // [64,320,64,64]
    float* out = (float*)d_out;

    // Phase 1: 64 i x 80 t-quads, 128 threads, 77.8 KB dynamic smem
    const int smem_bytes = (2 * NT * 32 * PITCH + NT * 512) * 4;  // 77824
    cudaFuncSetAttribute(compute_u_kernel,
                         cudaFuncAttributeMaxDynamicSharedMemorySize,
                         smem_bytes);
    compute_u_kernel<<<64 * 80, 128, smem_bytes>>>(M_emb, Ht, W);

    // Phase 2: one CTA per (b,i)
    iterate_kernel<<<512, 512>>>(m_init, out);
}